// round 17
// baseline (speedup 1.0000x reference)
#include <cuda_runtime.h>
#include <cuda_bf16.h>
#include <cstdint>

#define B_IMGS   32
#define NCELL    4096
#define NDET     12288
#define NCLS     80
#define TOPK     1024
#define NCAND    2048
#define NBINS    256
#define CNF_THR  0.5f
#define IOU_THR  0.4f
#define CLS_OFF  10000.0f
#define STRIDE_S 8.0f
#define NPAIRS   528              // upper-triangle (qblock, word) pairs per image
#define RANK_CTAS 8               // rank CTAs per image; partition by n&7

// ---------------- device scratch ----------------
__device__ float               g_srt[(size_t)B_IMGS * TOPK * 8];       // 1 MB
__device__ float4              g_box[(size_t)B_IMGS * TOPK];           // shifted boxes
__device__ float               g_area[(size_t)B_IMGS * TOPK];
__device__ unsigned int        g_mask[(size_t)B_IMGS * TOPK * 32];     // upper-tri written; lower-tri stays 0
__device__ unsigned int        g_any[B_IMGS * 32];                     // rowblock summary (reset by last CTA)
__device__ unsigned int        g_done[B_IMGS];                         // K2 completion counters (reset by last CTA)

__device__ __forceinline__ unsigned int ord_f32(float f) {
    unsigned int u = __float_as_uint(f);
    return (u & 0x80000000u) ? ~u : (u | 0x80000000u);
}
__device__ __forceinline__ unsigned int inv_ord(unsigned int v) {
    return (v & 0x80000000u) ? (v & 0x7FFFFFFFu) : ~v;
}
__device__ __forceinline__ int tri_off(int qb) { return 32 * qb - (qb * (qb - 1)) / 2; }

// ================= K1: fused select (redundant per CTA) + rank + gather ==========
// grid (RANK_CTAS, B_IMGS) x 1024. Each CTA rebuilds the candidate list in smem
// (set is deterministic; order irrelevant for rank), then processes candidates
// with (n & 7) == blockIdx.x.
__global__ void __launch_bounds__(1024) select_rank_kernel(const float* __restrict__ in) {
    __shared__ unsigned long long sk[NCAND];   // 16 KB
    __shared__ unsigned int hist[NBINS];
    __shared__ unsigned int scnt;
    __shared__ unsigned int sT;

    const int b = blockIdx.y, jcta = blockIdx.x, tid = threadIdx.x;
    const int lane = tid & 31;
    if (tid < NBINS) hist[tid] = 0u;
    if (tid == 0) scnt = 0u;
    __syncthreads();

    // objectness keys (registers) + histogram
    unsigned long long keys[12];
    #pragma unroll
    for (int k = 0; k < 12; ++k) {
        const int l = tid + k * 1024;          // 0..12287
        const int a = l >> 12;
        const int s = l & 4095;
        const float t4 = in[((size_t)b * 255 + (size_t)a * 85 + 4) * NCELL + s];
        const float conf = 1.0f / (1.0f + expf(-t4));
        const int n = (((s & 63) << 6) | (s >> 6)) * 3 + a;   // reference det order
        const float score = (conf > CNF_THR) ? conf : (-__int_as_float(0x7f800000));
        const unsigned int hi = ord_f32(score);
        keys[k] = ((unsigned long long)hi << 32)
                | (unsigned long long)(0xFFFFFFFFu - (unsigned int)n);
        if (hi >= 0xBF000000u) {
            unsigned int bin = (hi - 0xBF000000u) >> 15;
            if (bin > 255u) bin = 255u;
            atomicAdd(&hist[bin], 1u);
        }
    }
    __syncthreads();

    // warp 0: suffix-scan over 256 bins -> threshold bin T
    if (tid < 32) {
        unsigned int v[8];
        #pragma unroll
        for (int k = 0; k < 8; ++k) v[k] = hist[tid * 8 + k];
        unsigned int ls[9];
        ls[8] = 0u;
        #pragma unroll
        for (int k = 7; k >= 0; --k) ls[k] = ls[k + 1] + v[k];
        const unsigned int t = ls[0];
        unsigned int st = t;
        #pragma unroll
        for (int off = 1; off < 32; off <<= 1) {
            const unsigned int nn = __shfl_down_sync(0xFFFFFFFFu, st, off);
            if (tid + off < 32) st += nn;
        }
        const unsigned int after = st - t;
        if (tid == 0) sT = 0u;
        __syncwarp();
        #pragma unroll
        for (int k = 0; k < 8; ++k) {
            const unsigned int sfx = ls[k] + after;
            const unsigned int nxt = ls[k + 1] + after;
            if (sfx >= TOPK && nxt < TOPK) sT = (unsigned int)(tid * 8 + k);
        }
    }
    __syncthreads();
    const unsigned int T = sT;

    // compact survivors to smem (order nondeterministic; set deterministic)
    #pragma unroll
    for (int k = 0; k < 12; ++k) {
        const unsigned int hi = (unsigned int)(keys[k] >> 32);
        const bool surv = (hi >= 0xBF000000u) && (((hi - 0xBF000000u) >> 15) >= T);
        const unsigned int bal = __ballot_sync(0xFFFFFFFFu, surv);
        unsigned int base = 0;
        if (lane == 0 && bal) base = atomicAdd(&scnt, __popc(bal));
        base = __shfl_sync(0xFFFFFFFFu, base, 0);
        if (surv) {
            const unsigned int pos = base + __popc(bal & ((1u << lane) - 1u));
            if (pos < NCAND) sk[pos] = keys[k];
        }
    }
    __syncthreads();
    const int cnt = (scnt < NCAND) ? (int)scnt : NCAND;

    // zero-fill tail rows (only when cnt < TOPK); CTA 0 owns it
    if (jcta == 0) {
        for (int c = cnt + tid; c < TOPK; c += 1024) {
            float* o = g_srt + ((size_t)b * TOPK + c) * 8;
            *(float4*)(o)     = make_float4(0.f, 0.f, 0.f, 0.f);
            *(float4*)(o + 4) = make_float4(0.f, 0.f, 0.f, 0.f);
            g_box[(size_t)b * TOPK + c]  = make_float4(0.f, 0.f, 0.f, 0.f);
            g_area[(size_t)b * TOPK + c] = 0.f;
        }
    }

    // warp w scans its 64 slots; processes candidates with (n & 7) == jcta
    const int w = tid >> 5;
    for (int slot = w * 64; slot < w * 64 + 64; ++slot) {
        if (slot >= cnt) break;
        const unsigned long long key = sk[slot];                       // uniform per warp
        const unsigned int n = 0xFFFFFFFFu - (unsigned int)(key & 0xFFFFFFFFull);
        if ((int)(n & 7u) != jcta) continue;

        // exact rank (all keys distinct)
        int rk = 0;
        for (int j = lane; j < cnt; j += 32) rk += (int)(sk[j] > key);
        #pragma unroll
        for (int off = 16; off > 0; off >>= 1)
            rk += __shfl_down_sync(0xFFFFFFFFu, rk, off);
        rk = __shfl_sync(0xFFFFFFFFu, rk, 0);
        if (rk >= TOPK) continue;

        const unsigned int r = n / 3u;
        const unsigned int a = n - r * 3u;
        const unsigned int s = ((r & 63u) << 6) | (r >> 6);
        const float* p = in + ((size_t)b * 255 + (size_t)a * 85) * NCELL + s;

        // lane-parallel class argmax, first-occurrence tie-break
        unsigned long long best;
        {
            const float v0 = p[(5 + lane) * NCELL];
            best = ((unsigned long long)ord_f32(v0) << 32) | (unsigned long long)(255 - lane);
            const float v1 = p[(5 + lane + 32) * NCELL];
            const unsigned long long p1 =
                ((unsigned long long)ord_f32(v1) << 32) | (unsigned long long)(255 - (lane + 32));
            if (p1 > best) best = p1;
            if (lane < 16) {
                const float v2 = p[(5 + lane + 64) * NCELL];
                const unsigned long long p2 =
                    ((unsigned long long)ord_f32(v2) << 32) | (unsigned long long)(255 - (lane + 64));
                if (p2 > best) best = p2;
            }
            #pragma unroll
            for (int off = 16; off > 0; off >>= 1) {
                const unsigned long long ot = __shfl_down_sync(0xFFFFFFFFu, best, off);
                if (ot > best) best = ot;
            }
        }

        if (lane == 0) {
            const float t0 = p[0 * NCELL];
            const float t1 = p[1 * NCELL];
            const float t2 = p[2 * NCELL];
            const float t3 = p[3 * NCELL];

            const float conf  = __uint_as_float((unsigned int)(key >> 32) & 0x7FFFFFFFu);
            const float x_off = (float)((n >> 6) & 63);
            const float y_off = (float)(n & 63);
            const float cx = t0 + x_off, cy = t1 + y_off;
            const float hw = t2 * 0.5f,  hh = t3 * 0.5f;
            const float c0 = cx - hw, c1 = cy - hh, c2 = cx + hw, c3 = cy + hh;

            const int   bi = 255 - (int)(best & 0xFFull);
            const float bv = __uint_as_float(inv_ord((unsigned int)(best >> 32)));

            float* o = g_srt + ((size_t)b * TOPK + rk) * 8;
            *(float4*)(o)     = make_float4(c0, c1, c2, c3);
            *(float4*)(o + 4) = make_float4(conf, bv, (float)bi, 0.f);

            const float sh = (float)bi * CLS_OFF;
            g_box[(size_t)b * TOPK + rk]  = make_float4(c0 + sh, c1 + sh, c2 + sh, c3 + sh);
            g_area[(size_t)b * TOPK + rk] = (c2 - c0) * (c3 - c1);
        }
    }
}

// ================= K2: IoU mask + (last CTA) greedy + output =====================
// grid (17, B_IMGS) x 1024. Last-finishing CTA per image runs the greedy pass
// reading mask words from L2 (just written; heavy blocks rare).
__global__ void __launch_bounds__(1024) mask_greedy_kernel(float* __restrict__ out) {
    __shared__ float4 sbox[TOPK];   // 16 KB
    __shared__ float  sarea[TOPK];  //  4 KB
    __shared__ unsigned int svalid[32];
    __shared__ unsigned int skeepw[32];
    __shared__ unsigned int sany[32];
    __shared__ int s_last;

    const int b = blockIdx.y;
    const int tid = threadIdx.x;
    const int lane = tid & 31;
    const int w = tid >> 5;

    sbox[tid]  = g_box[(size_t)b * TOPK + tid];
    sarea[tid] = g_area[(size_t)b * TOPK + tid];
    __syncthreads();

    const int p = blockIdx.x * 32 + w;   // pair index
    if (p < NPAIRS) {
        const float rt = sqrtf(4225.0f - 8.0f * (float)p);
        int qb = (int)((65.0f - rt) * 0.5f);
        if (tri_off(qb + 1) <= p) qb++;
        if (tri_off(qb) > p) qb--;
        const int wd = qb + (p - tri_off(qb));
        const int q = (qb << 5) | lane;

        const float4 bx   = sbox[q];
        const float  myAe = sarea[q] + 1e-9f;
        const int j0 = wd << 5;

        unsigned int bits = 0;
        #pragma unroll 8
        for (int jj = 0; jj < 32; ++jj) {
            const int j = j0 + jj;
            const float4 ob = sbox[j];
            const float lx = fmaxf(bx.x, ob.x);
            const float ly = fmaxf(bx.y, ob.y);
            const float rx = fminf(bx.z, ob.z);
            const float ry = fminf(bx.w, ob.w);
            const float iw = fmaxf(rx - lx, 0.0f);
            const float ih = fmaxf(ry - ly, 0.0f);
            const float inter = iw * ih;
            const float denom = myAe + sarea[j] - inter;
            const bool hit = (denom > 0.0f) && (inter > IOU_THR * denom);
            if (hit) bits |= (1u << jj);
        }
        if (wd == qb) bits &= ~((2u << lane) - 1u);   // diagonal: only j > q
        g_mask[((size_t)b * TOPK + q) * 32 + wd] = bits;
        if (bits) atomicOr(&g_any[b * 32 + qb], bits);
    }

    // completion protocol: last CTA per image proceeds to greedy
    __threadfence();
    __syncthreads();
    if (tid == 0) s_last = (atomicAdd(&g_done[b], 1u) == 16) ? 1 : 0;
    __syncthreads();
    if (!s_last) return;
    __threadfence();

    // ---- greedy (last CTA only) ----
    if (tid < 32) sany[tid] = g_any[b * 32 + tid];

    const float* o = g_srt + ((size_t)b * TOPK + tid) * 8;
    const float4 lo = *(const float4*)(o);
    const float4 hi = *(const float4*)(o + 4);
    const unsigned int bal = __ballot_sync(0xFFFFFFFFu, hi.x > CNF_THR);
    if (lane == 0) svalid[w] = bal;
    __syncthreads();

    if (tid < 32) {
        const unsigned int* mb = g_mask + (size_t)b * TOPK * 32;
        unsigned int sup = 0, keepw = 0;
        for (int blk = 0; blk < 32; ++blk) {
            const unsigned int ext = __shfl_sync(0xFFFFFFFFu, sup, blk);
            const unsigned int vv  = svalid[blk];

            unsigned int keepmask;
            if (sany[blk] == 0) {
                keepmask = vv & ~ext;        // exact fast path: rowblock has no bits
            } else {
                keepmask = 0;
                if (tid == 0) {
                    unsigned int rr[32];
                    #pragma unroll
                    for (int i = 0; i < 32; ++i)
                        rr[i] = mb[(size_t)(blk * 32 + i) * 32 + blk];
                    unsigned int s = ext;
                    #pragma unroll
                    for (int i = 0; i < 32; ++i) {
                        const unsigned int kb = ((~s >> i) & (vv >> i)) & 1u;
                        keepmask |= kb << i;
                        s |= rr[i] & (0u - kb);
                    }
                }
                keepmask = __shfl_sync(0xFFFFFFFFu, keepmask, 0);
                #pragma unroll
                for (int i = 0; i < 32; ++i)
                    sup |= mb[(size_t)(blk * 32 + i) * 32 + tid] & (0u - ((keepmask >> i) & 1u));
            }
            if (tid == blk) keepw = keepmask;
        }
        skeepw[tid] = keepw;
    }
    __syncthreads();

    const bool kp = (skeepw[w] >> lane) & 1u;
    const float f = kp ? STRIDE_S : 0.0f;
    float* od = out + ((size_t)b * TOPK + tid) * 7;
    od[0] = f * lo.x; od[1] = f * lo.y; od[2] = f * lo.z; od[3] = f * lo.w;
    od[4] = f * hi.x; od[5] = f * hi.y; od[6] = f * hi.z;
    out[(size_t)B_IMGS * TOPK * 7 + (size_t)b * TOPK + tid] = kp ? 1.0f : 0.0f;

    // reset scratch for next replay (zero-at-entry invariant)
    if (tid < 32) g_any[b * 32 + tid] = 0u;
    if (tid == 0) g_done[b] = 0u;
}

// ================= launcher =================
extern "C" void kernel_launch(void* const* d_in, const int* in_sizes, int n_in,
                              void* d_out, int out_size) {
    const float* in = (const float*)d_in[0];
    float* out = (float*)d_out;

    select_rank_kernel<<<dim3(RANK_CTAS, B_IMGS), 1024>>>(in);
    mask_greedy_kernel<<<dim3((NPAIRS + 31) / 32, B_IMGS), 1024>>>(out);
}